// round 2
// baseline (speedup 1.0000x reference)
#include <cuda_runtime.h>
#include <math.h>

// NaiveFourierKANLayer: y[N,256] = sum_{i,k} cos(x[n,i]*(k+1))*Wc[o,i,k]
//                                + sum_{i,k} sin(x[n,i]*(k+1))*Ws[o,i,k] + bias[o]
// N=32768, INPUTDIM=64, OUTDIM=256, GRIDSIZE=32.
// Fused SGEMM: M=32768, N=256, K=4096 (features generated on the fly via
// angle-addition recurrence to avoid the MUFU bottleneck).

#define NROWS   32768
#define INDIM   64
#define OUTDIM  256
#define GSIZE   32

#define BM 128
#define BN 128
#define WPAD 132   // 64 x 132 floats, pad to dodge 32-way STS conflicts

__global__ __launch_bounds__(256, 2)
void kan_fused_sgemm(const float* __restrict__ x,
                     const float* __restrict__ w,      // [2][256][64][32]
                     const float* __restrict__ bias,   // [256]
                     float* __restrict__ out) {        // [N][256]
    extern __shared__ float smem[];
    float* As = smem;              // [64][BM]   feature tile (f-major)
    float* Ws = smem + 64 * BM;    // [64][WPAD] weight tile

    const int row0 = blockIdx.x * BM;
    const int col0 = blockIdx.y * BN;
    const int t  = threadIdx.x;
    const int tx = t & 15;         // output-col group
    const int ty = t >> 4;         // row group

    float acc[8][8];
    #pragma unroll
    for (int r = 0; r < 8; ++r)
        #pragma unroll
        for (int c = 0; c < 8; ++c) acc[r][c] = 0.0f;

    for (int i = 0; i < INDIM; ++i) {
        // ---- Load W tile: 64 features x 128 output cols ----
        // idx -> f = idx & 63 (= type*32 + k), o = idx >> 6.
        // Warp covers one (type,o) row of 32 contiguous k floats: fully coalesced LDG.
        #pragma unroll
        for (int j = 0; j < 32; ++j) {
            int idx  = t + j * 256;
            int f    = idx & 63;
            int o    = idx >> 6;
            int type = f >> 5;
            int k    = f & 31;
            Ws[f * WPAD + o] =
                w[(((type * OUTDIM) + col0 + o) * INDIM + i) * GSIZE + k];
        }

        // ---- Generate feature tile: rows of cos(kx), sin(kx), k=1..32 ----
        if (t < BM) {
            float xv = x[(row0 + t) * INDIM + i];
            float s1, c1;
            sincosf(xv, &s1, &c1);
            float ck = c1, sk = s1;
            #pragma unroll
            for (int k = 0; k < GSIZE; ++k) {
                As[k * BM + t]           = ck;   // cos((k+1)x)
                As[(GSIZE + k) * BM + t] = sk;   // sin((k+1)x)
                float cn = fmaf(ck, c1, -sk * s1);
                sk       = fmaf(sk, c1,  ck * s1);
                ck = cn;
            }
        }
        __syncthreads();

        // ---- Inner GEMM over this 64-feature chunk ----
        #pragma unroll 8
        for (int kk = 0; kk < 64; ++kk) {
            float4 a0 = *(const float4*)&As[kk * BM + ty * 8];
            float4 a1 = *(const float4*)&As[kk * BM + ty * 8 + 4];
            float4 b0 = *(const float4*)&Ws[kk * WPAD + tx * 8];
            float4 b1 = *(const float4*)&Ws[kk * WPAD + tx * 8 + 4];
            float a[8] = {a0.x, a0.y, a0.z, a0.w, a1.x, a1.y, a1.z, a1.w};
            float b[8] = {b0.x, b0.y, b0.z, b0.w, b1.x, b1.y, b1.z, b1.w};
            #pragma unroll
            for (int r = 0; r < 8; ++r)
                #pragma unroll
                for (int c = 0; c < 8; ++c)
                    acc[r][c] = fmaf(a[r], b[c], acc[r][c]);
        }
        __syncthreads();
    }

    // ---- Epilogue: add bias, write out ----
    #pragma unroll
    for (int r = 0; r < 8; ++r) {
        int row = row0 + ty * 8 + r;
        #pragma unroll
        for (int c = 0; c < 8; c += 4) {
            int col = col0 + tx * 8 + c;
            float4 v;
            v.x = acc[r][c + 0] + bias[col + 0];
            v.y = acc[r][c + 1] + bias[col + 1];
            v.z = acc[r][c + 2] + bias[col + 2];
            v.w = acc[r][c + 3] + bias[col + 3];
            *(float4*)&out[row * OUTDIM + col] = v;
        }
    }
}

extern "C" void kernel_launch(void* const* d_in, const int* in_sizes, int n_in,
                              void* d_out, int out_size) {
    const float* x    = (const float*)d_in[0];   // [32768][64]
    const float* w    = (const float*)d_in[1];   // [2][256][64][32]
    const float* bias = (const float*)d_in[2];   // [1][256]
    float* out        = (float*)d_out;           // [32768][256]

    const int smem_bytes = (64 * BM + 64 * WPAD) * sizeof(float);  // 66,560 B
    cudaFuncSetAttribute(kan_fused_sgemm,
                         cudaFuncAttributeMaxDynamicSharedMemorySize, smem_bytes);

    dim3 grid(NROWS / BM, OUTDIM / BN);  // (256, 2)
    kan_fused_sgemm<<<grid, 256, smem_bytes>>>(x, w, bias, out);
}

// round 4
// speedup vs baseline: 2.6848x; 2.6848x over previous
#include <cuda_runtime.h>
#include <cstdint>
#include <math.h>

// NaiveFourierKANLayer via classic tensor-core path (mma.sync bf16, split x3):
//   y[32768,256] = A[32768,4096] @ W[4096,256] + bias
// A[n, f] generated on the fly: f in [0,64) per input dim i:
//   f=0..31  : cos((f+1)*x[n,i]),  f=32..63 : sin((f-31)*x[n,i])
// Split-bf16: v = vh + vl (bf16 each); y ~= Ah*Wh + Al*Wh + Ah*Wl  (fp32 accum)

#define NROWS   32768
#define INDIM   64
#define OUTDIM  256

// ---------- helpers ----------
__device__ __forceinline__ uint32_t smem_u32(const void* p) {
    uint32_t a;
    asm("{ .reg .u64 t; cvta.to.shared.u64 t, %1; cvt.u32.u64 %0, t; }" : "=r"(a) : "l"(p));
    return a;
}
__device__ __forceinline__ uint32_t pack_bf(float e0, float e1) {   // low half = e0
    uint32_t r;
    asm("cvt.rn.bf16x2.f32 %0, %1, %2;" : "=r"(r) : "f"(e1), "f"(e0));
    return r;
}
__device__ __forceinline__ float bf_low(uint32_t w)  { return __uint_as_float(w << 16); }
__device__ __forceinline__ float bf_high(uint32_t w) { return __uint_as_float(w & 0xFFFF0000u); }
__device__ __forceinline__ uint32_t swz(uint32_t off) { return off ^ ((off >> 3) & 0x70); }

__device__ __forceinline__ void cpa16(uint32_t dst, const void* src) {
    asm volatile("cp.async.cg.shared.global [%0], [%1], 16;" :: "r"(dst), "l"(src) : "memory");
}
#define CP_COMMIT() asm volatile("cp.async.commit_group;" ::: "memory")
#define CP_WAIT(n)  asm volatile("cp.async.wait_group %0;" :: "n"(n) : "memory")

__device__ __forceinline__ void ldsm4(uint32_t* r, uint32_t addr) {
    asm volatile("ldmatrix.sync.aligned.m8n8.x4.shared.b16 {%0,%1,%2,%3}, [%4];"
                 : "=r"(r[0]), "=r"(r[1]), "=r"(r[2]), "=r"(r[3]) : "r"(addr));
}
__device__ __forceinline__ void mma_bf16(float* d, const uint32_t* a, uint32_t b0, uint32_t b1) {
    asm volatile("mma.sync.aligned.m16n8k16.row.col.f32.bf16.bf16.f32 "
                 "{%0,%1,%2,%3},{%4,%5,%6,%7},{%8,%9},{%0,%1,%2,%3};"
                 : "+f"(d[0]), "+f"(d[1]), "+f"(d[2]), "+f"(d[3])
                 : "r"(a[0]), "r"(a[1]), "r"(a[2]), "r"(a[3]), "r"(b0), "r"(b1));
}

// ---------- pre-swizzled W tiles ----------
// Layout: g_wt[i][split(hi=0,lo=1)][slab(o>>7)][ swz((o&127)*128 + f*2) ]
// per i: 64KB; per slab: 16KB (128 o-rows x 64 bf16 features)
__device__ __align__(1024) unsigned char g_wt[64 * 65536];

__global__ void kan_wprep(const float* __restrict__ w) {
    const int i = blockIdx.x;          // input dim
    const int o = threadIdx.x;         // output (256 threads)
    // w[type][o][i][k] : ((type*256 + o)*64 + i)*32 + k
    const float* pc = w + ((size_t)(0 * 256 + o) * 64 + i) * 32;   // cos weights k=0..31
    const float* ps = w + ((size_t)(1 * 256 + o) * 64 + i) * 32;   // sin weights
    unsigned char* hi = g_wt + (size_t)i * 65536 + (o >> 7) * 16384;
    unsigned char* lo = hi + 32768;
    const uint32_t rowb = (uint32_t)(o & 127) * 128;

    #pragma unroll
    for (int half = 0; half < 2; ++half) {           // 0: cos (f 0..31), 1: sin (f 32..63)
        const float* src = half ? ps : pc;
        #pragma unroll
        for (int g = 0; g < 4; ++g) {                // 8 features per uint4
            float4 v0 = *(const float4*)(src + g * 8);
            float4 v1 = *(const float4*)(src + g * 8 + 4);
            float e[8] = {v0.x, v0.y, v0.z, v0.w, v1.x, v1.y, v1.z, v1.w};
            uint32_t h[4], l[4];
            #pragma unroll
            for (int p = 0; p < 4; ++p) {
                h[p] = pack_bf(e[2*p], e[2*p+1]);
                l[p] = pack_bf(e[2*p] - bf_low(h[p]), e[2*p+1] - bf_high(h[p]));
            }
            uint32_t off = swz(rowb + half * 64 + g * 16);
            *(uint4*)(hi + off) = make_uint4(h[0], h[1], h[2], h[3]);
            *(uint4*)(lo + off) = make_uint4(l[0], l[1], l[2], l[3]);
        }
    }
}

// ---------- main kernel ----------
// SMEM (dynamic, 128KB):
//   A tiles: buf b: hi @ b*32768 (16KB), lo @ +16384
//   W tiles: buf b: hi @ 65536 + b*32768, lo @ +16384
#define SA_HI(b) ((uint32_t)(b) * 32768u)
#define SA_LO(b) (SA_HI(b) + 16384u)
#define SW_HI(b) (65536u + (uint32_t)(b) * 32768u)
#define SW_LO(b) (SW_HI(b) + 16384u)
#define SMEM_SZ  131072

__global__ __launch_bounds__(256, 1)
void kan_mma(const float* __restrict__ x, const float* __restrict__ bias,
             float* __restrict__ out) {
    extern __shared__ __align__(1024) unsigned char sm[];
    const uint32_t sb = smem_u32(sm);
    const int t = threadIdx.x, lane = t & 31, wid = t >> 5;
    const int row0 = blockIdx.x * 128, col0 = blockIdx.y * 128;

    // ---- producer (A-gen) identity: 2 threads per row, each 16 k-values ----
    const int ar_gen = t & 127;        // row
    const int ah_gen = t >> 7;         // k-half: 0 -> k=1..16, 1 -> k=17..32
    const uint32_t genrow = (uint32_t)ar_gen * 128;
    const uint32_t genxm  = ((uint32_t)ar_gen & 7) << 4;

    // ---- W copy identity: 4 chunks of 16B per split ----
    const unsigned char* wslab = g_wt + (size_t)(col0 >> 7) * 16384;

    // ---- MMA identity ----
    const int wm = wid & 3, wn = wid >> 2;         // 4 x 2 warp grid
    const int m0 = wm * 32, n0 = wn * 64;
    // A ldmatrix: row = m0 + mt*16 + (lane&15); col16 add = (lane&16)?16:0
    const int a_r   = m0 + (lane & 15);
    const uint32_t a_kadd = (lane & 16) ? 16u : 0u;
    const uint32_t a_xm   = ((uint32_t)a_r & 7) << 4;
    // B ldmatrix: row = n0 + pair*16 + (lane&7) + ((lane&16)?8:0); col add = (lane&8)?16:0
    const int b_r   = n0 + (lane & 7) + ((lane & 16) ? 8 : 0);
    const uint32_t b_kadd = (lane & 8) ? 16u : 0u;
    const uint32_t b_xm   = ((uint32_t)b_r & 7) << 4;

    float acc[2][8][4];
    #pragma unroll
    for (int mt = 0; mt < 2; ++mt)
        #pragma unroll
        for (int nt = 0; nt < 8; ++nt)
            #pragma unroll
            for (int e = 0; e < 4; ++e) acc[mt][nt][e] = 0.0f;

    // ---------- lambdas as macros ----------
    // generate A(i) into buffer b
    #define GEN_A(ii, bb) do {                                                   \
        float xv = __ldg(&x[(size_t)(row0 + ar_gen) * INDIM + (ii)]);            \
        float s1, c1; sincosf(xv, &s1, &c1);                                     \
        float ck, sk;                                                            \
        if (ah_gen == 0) { ck = c1; sk = s1; }                                   \
        else {                                                                   \
            float c2 = fmaf(c1, c1, -(s1 * s1)), s2 = 2.0f * s1 * c1;            \
            float c4 = fmaf(c2, c2, -(s2 * s2)), s4 = 2.0f * s2 * c2;            \
            float c8 = fmaf(c4, c4, -(s4 * s4)), s8 = 2.0f * s4 * c4;            \
            float c16 = fmaf(c8, c8, -(s8 * s8)), s16 = 2.0f * s8 * c8;          \
            ck = fmaf(c16, c1, -(s16 * s1)); sk = fmaf(s16, c1, c16 * s1);       \
        }                                                                        \
        uint32_t chv[8], clv[8], shv[8], slv[8];                                 \
        _Pragma("unroll")                                                        \
        for (int p = 0; p < 8; ++p) {                                            \
            float cc0 = ck, ss0 = sk;                                            \
            float cA = fmaf(ck, c1, -(sk * s1));                                 \
            float sA = fmaf(sk, c1, ck * s1);                                    \
            chv[p] = pack_bf(cc0, cA);                                           \
            clv[p] = pack_bf(cc0 - bf_low(chv[p]), cA - bf_high(chv[p]));        \
            shv[p] = pack_bf(ss0, sA);                                           \
            slv[p] = pack_bf(ss0 - bf_low(shv[p]), sA - bf_high(shv[p]));        \
            ck = fmaf(cA, c1, -(sA * s1)); sk = fmaf(sA, c1, cA * s1);           \
        }                                                                        \
        _Pragma("unroll")                                                        \
        for (int g = 0; g < 2; ++g) {                                            \
            uint32_t cb = (uint32_t)ah_gen * 32 + g * 16;                        \
            uint32_t oc = genrow + (cb ^ genxm);                                 \
            uint32_t os = genrow + ((cb + 64u) ^ genxm);                         \
            *(uint4*)(sm + SA_HI(bb) + oc) = make_uint4(chv[4*g], chv[4*g+1], chv[4*g+2], chv[4*g+3]); \
            *(uint4*)(sm + SA_LO(bb) + oc) = make_uint4(clv[4*g], clv[4*g+1], clv[4*g+2], clv[4*g+3]); \
            *(uint4*)(sm + SA_HI(bb) + os) = make_uint4(shv[4*g], shv[4*g+1], shv[4*g+2], shv[4*g+3]); \
            *(uint4*)(sm + SA_LO(bb) + os) = make_uint4(slv[4*g], slv[4*g+1], slv[4*g+2], slv[4*g+3]); \
        }                                                                        \
    } while (0)

    // kick cp.async copy of W(i) into buffer b (hi+lo = 32KB; 8 chunks/thread)
    #define KICK_W(ii, bb) do {                                                  \
        const unsigned char* wh_ = wslab + (size_t)(ii) * 65536;                 \
        const unsigned char* wl_ = wh_ + 32768;                                  \
        _Pragma("unroll")                                                        \
        for (int j = 0; j < 4; ++j) {                                            \
            uint32_t off_ = ((uint32_t)t + j * 256u) * 16u;                      \
            cpa16(sb + SW_HI(bb) + off_, wh_ + off_);                            \
            cpa16(sb + SW_LO(bb) + off_, wl_ + off_);                            \
        }                                                                        \
        CP_COMMIT();                                                             \
    } while (0)

    // ---------- pipeline ----------
    KICK_W(0, 0);
    GEN_A(0, 0);

    #pragma unroll 1
    for (int i = 0; i < INDIM; ++i) {
        const int b = i & 1;
        __syncthreads();                              // prev compute done with bufs b^1
        if (i + 1 < INDIM) {
            KICK_W(i + 1, b ^ 1);
            GEN_A(i + 1, b ^ 1);
        }
        if (i + 1 < INDIM) { CP_WAIT(1); } else { CP_WAIT(0); }
        __syncthreads();                              // A(i) + W(i) visible

        // ---- compute on bufs b ----
        const uint32_t Ah = sb + SA_HI(b), Al = sb + SA_LO(b);
        const uint32_t Wh = sb + SW_HI(b), Wl = sb + SW_LO(b);
        #pragma unroll
        for (int ks = 0; ks < 4; ++ks) {
            const uint32_t kb = ks * 32;
            const uint32_t acol = (kb + a_kadd) ^ a_xm;
            const uint32_t bcol = (kb + b_kadd) ^ b_xm;
            uint32_t ahr[2][4], alr[2][4];
            #pragma unroll
            for (int mt = 0; mt < 2; ++mt) {
                uint32_t ro = (uint32_t)(a_r + mt * 16) * 128 + acol;
                ldsm4(ahr[mt], Ah + ro);
                ldsm4(alr[mt], Al + ro);
            }
            uint32_t bhr[4][4], blr[4][4];
            #pragma unroll
            for (int pr = 0; pr < 4; ++pr) {
                uint32_t ro = (uint32_t)(b_r + pr * 16) * 128 + bcol;
                ldsm4(bhr[pr], Wh + ro);
                ldsm4(blr[pr], Wl + ro);
            }
            #pragma unroll
            for (int mt = 0; mt < 2; ++mt)
                #pragma unroll
                for (int nt = 0; nt < 8; ++nt) {
                    const int pr = nt >> 1, su = (nt & 1) * 2;
                    mma_bf16(acc[mt][nt], ahr[mt], bhr[pr][su], bhr[pr][su + 1]);
                    mma_bf16(acc[mt][nt], alr[mt], bhr[pr][su], bhr[pr][su + 1]);
                    mma_bf16(acc[mt][nt], ahr[mt], blr[pr][su], blr[pr][su + 1]);
                }
        }
    }

    // ---------- epilogue ----------
    const int grp = lane >> 2, tig = lane & 3;
    #pragma unroll
    for (int nt = 0; nt < 8; ++nt) {
        const int cg = col0 + n0 + nt * 8 + 2 * tig;
        const float2 bs = *(const float2*)&bias[cg];
        #pragma unroll
        for (int mt = 0; mt < 2; ++mt) {
            const int rg = row0 + m0 + mt * 16 + grp;
            float2 v0 = make_float2(acc[mt][nt][0] + bs.x, acc[mt][nt][1] + bs.y);
            float2 v1 = make_float2(acc[mt][nt][2] + bs.x, acc[mt][nt][3] + bs.y);
            *(float2*)&out[(size_t)rg * OUTDIM + cg]       = v0;
            *(float2*)&out[(size_t)(rg + 8) * OUTDIM + cg] = v1;
        }
    }
    #undef GEN_A
    #undef KICK_W
}

extern "C" void kernel_launch(void* const* d_in, const int* in_sizes, int n_in,
                              void* d_out, int out_size) {
    const float* x    = (const float*)d_in[0];   // [32768][64]
    const float* w    = (const float*)d_in[1];   // [2][256][64][32]
    const float* bias = (const float*)d_in[2];   // [1][256]
    float* out        = (float*)d_out;           // [32768][256]

    cudaFuncSetAttribute(kan_mma, cudaFuncAttributeMaxDynamicSharedMemorySize, SMEM_SZ);

    kan_wprep<<<64, 256>>>(w);
    dim3 grid(NROWS / 128, OUTDIM / 128);        // (256, 2)
    kan_mma<<<grid, 256, SMEM_SZ>>>(x, bias, out);
}

// round 6
// speedup vs baseline: 2.9696x; 1.1061x over previous
#include <cuda_runtime.h>
#include <cstdint>
#include <math.h>

// NaiveFourierKANLayer via classic tensor-core path (mma.sync bf16, split x3):
//   y[32768,256] = A[32768,4096] @ W[4096,256] + bias
// R5: 96KB smem (A single-buffered, W double-buffered) + launch_bounds(256,2)
//     so 2 CTAs co-reside per SM and cover each other's A-gen bubbles.

#define NROWS   32768
#define INDIM   64
#define OUTDIM  256

// ---------- helpers ----------
__device__ __forceinline__ uint32_t smem_u32(const void* p) {
    uint32_t a;
    asm("{ .reg .u64 t; cvta.to.shared.u64 t, %1; cvt.u32.u64 %0, t; }" : "=r"(a) : "l"(p));
    return a;
}
__device__ __forceinline__ uint32_t pack_bf(float e0, float e1) {   // low half = e0
    uint32_t r;
    asm("cvt.rn.bf16x2.f32 %0, %1, %2;" : "=r"(r) : "f"(e1), "f"(e0));
    return r;
}
__device__ __forceinline__ float bf_low(uint32_t w)  { return __uint_as_float(w << 16); }
__device__ __forceinline__ float bf_high(uint32_t w) { return __uint_as_float(w & 0xFFFF0000u); }
__device__ __forceinline__ uint32_t swz(uint32_t off) { return off ^ ((off >> 3) & 0x70); }

__device__ __forceinline__ void cpa16(uint32_t dst, const void* src) {
    asm volatile("cp.async.cg.shared.global [%0], [%1], 16;" :: "r"(dst), "l"(src) : "memory");
}
#define CP_COMMIT() asm volatile("cp.async.commit_group;" ::: "memory")
#define CP_WAIT(n)  asm volatile("cp.async.wait_group %0;" :: "n"(n) : "memory")

__device__ __forceinline__ void ldsm4(uint32_t* r, uint32_t addr) {
    asm volatile("ldmatrix.sync.aligned.m8n8.x4.shared.b16 {%0,%1,%2,%3}, [%4];"
                 : "=r"(r[0]), "=r"(r[1]), "=r"(r[2]), "=r"(r[3]) : "r"(addr));
}
__device__ __forceinline__ void mma_bf16(float* d, const uint32_t* a, uint32_t b0, uint32_t b1) {
    asm volatile("mma.sync.aligned.m16n8k16.row.col.f32.bf16.bf16.f32 "
                 "{%0,%1,%2,%3},{%4,%5,%6,%7},{%8,%9},{%0,%1,%2,%3};"
                 : "+f"(d[0]), "+f"(d[1]), "+f"(d[2]), "+f"(d[3])
                 : "r"(a[0]), "r"(a[1]), "r"(a[2]), "r"(a[3]), "r"(b0), "r"(b1));
}

// ---------- pre-swizzled W tiles ----------
// Layout: g_wt[i][split(hi=0,lo=1)][slab(o>>7)][ swz((o&127)*128 + f*2) ]
// per i: 64KB; per slab: 16KB (128 o-rows x 64 bf16 features)
__device__ __align__(1024) unsigned char g_wt[64 * 65536];

__global__ void kan_wprep(const float* __restrict__ w) {
    const int i = blockIdx.x;          // input dim
    const int o = threadIdx.x;         // output (256 threads)
    const float* pc = w + ((size_t)(0 * 256 + o) * 64 + i) * 32;   // cos weights
    const float* ps = w + ((size_t)(1 * 256 + o) * 64 + i) * 32;   // sin weights
    unsigned char* hi = g_wt + (size_t)i * 65536 + (o >> 7) * 16384;
    unsigned char* lo = hi + 32768;
    const uint32_t rowb = (uint32_t)(o & 127) * 128;

    #pragma unroll
    for (int half = 0; half < 2; ++half) {           // 0: cos, 1: sin
        const float* src = half ? ps : pc;
        #pragma unroll
        for (int g = 0; g < 4; ++g) {
            float4 v0 = *(const float4*)(src + g * 8);
            float4 v1 = *(const float4*)(src + g * 8 + 4);
            float e[8] = {v0.x, v0.y, v0.z, v0.w, v1.x, v1.y, v1.z, v1.w};
            uint32_t h[4], l[4];
            #pragma unroll
            for (int p = 0; p < 4; ++p) {
                h[p] = pack_bf(e[2*p], e[2*p+1]);
                l[p] = pack_bf(e[2*p] - bf_low(h[p]), e[2*p+1] - bf_high(h[p]));
            }
            uint32_t off = swz(rowb + half * 64 + g * 16);
            *(uint4*)(hi + off) = make_uint4(h[0], h[1], h[2], h[3]);
            *(uint4*)(lo + off) = make_uint4(l[0], l[1], l[2], l[3]);
        }
    }
}

// ---------- main kernel ----------
// SMEM (dynamic, 96KB):
//   A tile (single buffer): hi @ 0 (16KB), lo @ 16384
//   W tiles (double):       buf b hi @ 32768 + b*32768, lo @ +16384
#define SA_HI    0u
#define SA_LO    16384u
#define SW_HI(b) (32768u + (uint32_t)(b) * 32768u)
#define SW_LO(b) (SW_HI(b) + 16384u)
#define SMEM_SZ  98304

__global__ __launch_bounds__(256, 2)
void kan_mma(const float* __restrict__ x, const float* __restrict__ bias,
             float* __restrict__ out) {
    extern __shared__ __align__(1024) unsigned char sm[];
    const uint32_t sb = smem_u32(sm);
    const int t = threadIdx.x, lane = t & 31, wid = t >> 5;
    const int row0 = blockIdx.x * 128, col0 = blockIdx.y * 128;

    // ---- producer (A-gen) identity: 2 threads per row, each 16 k-values ----
    const int ar_gen = t & 127;        // row
    const int ah_gen = t >> 7;         // k-half: 0 -> k=1..16, 1 -> k=17..32
    const uint32_t genrow = (uint32_t)ar_gen * 128;
    const uint32_t genxm  = ((uint32_t)ar_gen & 7) << 4;

    const unsigned char* wslab = g_wt + (size_t)(col0 >> 7) * 16384;

    // ---- MMA identity ----
    const int wm = wid & 3, wn = wid >> 2;         // 4 x 2 warp grid
    const int m0 = wm * 32, n0 = wn * 64;
    const int a_r   = m0 + (lane & 15);
    const uint32_t a_kadd = (lane & 16) ? 16u : 0u;
    const uint32_t a_xm   = ((uint32_t)a_r & 7) << 4;
    const int b_r   = n0 + (lane & 7) + ((lane & 16) ? 8 : 0);
    const uint32_t b_kadd = (lane & 8) ? 16u : 0u;
    const uint32_t b_xm   = ((uint32_t)b_r & 7) << 4;

    float acc[2][8][4];
    #pragma unroll
    for (int mt = 0; mt < 2; ++mt)
        #pragma unroll
        for (int nt = 0; nt < 8; ++nt)
            #pragma unroll
            for (int e = 0; e < 4; ++e) acc[mt][nt][e] = 0.0f;

    // generate A(i) into the single A buffer
    #define GEN_A(ii) do {                                                       \
        float xv = __ldg(&x[(size_t)(row0 + ar_gen) * INDIM + (ii)]);            \
        float s1, c1; sincosf(xv, &s1, &c1);                                     \
        float ck, sk;                                                            \
        if (ah_gen == 0) { ck = c1; sk = s1; }                                   \
        else {                                                                   \
            float c2 = fmaf(c1, c1, -(s1 * s1)), s2 = 2.0f * s1 * c1;            \
            float c4 = fmaf(c2, c2, -(s2 * s2)), s4 = 2.0f * s2 * c2;            \
            float c8 = fmaf(c4, c4, -(s4 * s4)), s8 = 2.0f * s4 * c4;            \
            float c16 = fmaf(c8, c8, -(s8 * s8)), s16 = 2.0f * s8 * c8;          \
            ck = fmaf(c16, c1, -(s16 * s1)); sk = fmaf(s16, c1, c16 * s1);       \
        }                                                                        \
        uint32_t chv[8], clv[8], shv[8], slv[8];                                 \
        _Pragma("unroll")                                                        \
        for (int p = 0; p < 8; ++p) {                                            \
            float cc0 = ck, ss0 = sk;                                            \
            float cA = fmaf(ck, c1, -(sk * s1));                                 \
            float sA = fmaf(sk, c1, ck * s1);                                    \
            chv[p] = pack_bf(cc0, cA);                                           \
            clv[p] = pack_bf(cc0 - bf_low(chv[p]), cA - bf_high(chv[p]));        \
            shv[p] = pack_bf(ss0, sA);                                           \
            slv[p] = pack_bf(ss0 - bf_low(shv[p]), sA - bf_high(shv[p]));        \
            ck = fmaf(cA, c1, -(sA * s1)); sk = fmaf(sA, c1, cA * s1);           \
        }                                                                        \
        _Pragma("unroll")                                                        \
        for (int g = 0; g < 2; ++g) {                                            \
            uint32_t cb = (uint32_t)ah_gen * 32 + g * 16;                        \
            uint32_t oc = genrow + (cb ^ genxm);                                 \
            uint32_t os = genrow + ((cb + 64u) ^ genxm);                         \
            *(uint4*)(sm + SA_HI + oc) = make_uint4(chv[4*g], chv[4*g+1], chv[4*g+2], chv[4*g+3]); \
            *(uint4*)(sm + SA_LO + oc) = make_uint4(clv[4*g], clv[4*g+1], clv[4*g+2], clv[4*g+3]); \
            *(uint4*)(sm + SA_HI + os) = make_uint4(shv[4*g], shv[4*g+1], shv[4*g+2], shv[4*g+3]); \
            *(uint4*)(sm + SA_LO + os) = make_uint4(slv[4*g], slv[4*g+1], slv[4*g+2], slv[4*g+3]); \
        }                                                                        \
    } while (0)

    // kick cp.async copy of W(i) into W buffer b (hi+lo = 32KB)
    #define KICK_W(ii, bb) do {                                                  \
        const unsigned char* wh_ = wslab + (size_t)(ii) * 65536;                 \
        const unsigned char* wl_ = wh_ + 32768;                                  \
        _Pragma("unroll")                                                        \
        for (int j = 0; j < 4; ++j) {                                            \
            uint32_t off_ = ((uint32_t)t + j * 256u) * 16u;                      \
            cpa16(sb + SW_HI(bb) + off_, wh_ + off_);                            \
            cpa16(sb + SW_LO(bb) + off_, wl_ + off_);                            \
        }                                                                        \
        CP_COMMIT();                                                             \
    } while (0)

    // ---------- pipeline ----------
    #pragma unroll 1
    for (int i = 0; i < INDIM; ++i) {
        const int wb = i & 1;
        __syncthreads();                       // compute(i-1) done: A free, W(wb^1) free
        if (i == 0) KICK_W(0, 0);
        if (i + 1 < INDIM) KICK_W(i + 1, wb ^ 1);
        GEN_A(i);
        if (i + 1 < INDIM) { CP_WAIT(1); } else { CP_WAIT(0); }
        __syncthreads();                       // A(i) + W(i) visible

        // ---- compute on A + W(wb) ----
        const uint32_t Ah = sb + SA_HI, Al = sb + SA_LO;
        const uint32_t Wh = sb + SW_HI(wb), Wl = sb + SW_LO(wb);
        #pragma unroll
        for (int ks = 0; ks < 4; ++ks) {
            const uint32_t kb = ks * 32;
            const uint32_t acol = (kb + a_kadd) ^ a_xm;
            const uint32_t bcol = (kb + b_kadd) ^ b_xm;
            uint32_t ahr[2][4], alr[2][4];
            #pragma unroll
            for (int mt = 0; mt < 2; ++mt) {
                uint32_t ro = (uint32_t)(a_r + mt * 16) * 128 + acol;
                ldsm4(ahr[mt], Ah + ro);
                ldsm4(alr[mt], Al + ro);
            }
            #pragma unroll
            for (int pr = 0; pr < 4; ++pr) {
                uint32_t bh[4], bl[4];
                uint32_t ro = (uint32_t)(b_r + pr * 16) * 128 + bcol;
                ldsm4(bh, Wh + ro);
                ldsm4(bl, Wl + ro);
                #pragma unroll
                for (int mt = 0; mt < 2; ++mt)
                    #pragma unroll
                    for (int h = 0; h < 2; ++h) {
                        float* d = acc[mt][pr * 2 + h];
                        mma_bf16(d, ahr[mt], bh[h * 2], bh[h * 2 + 1]);
                        mma_bf16(d, alr[mt], bh[h * 2], bh[h * 2 + 1]);
                        mma_bf16(d, ahr[mt], bl[h * 2], bl[h * 2 + 1]);
                    }
            }
        }
    }

    // ---------- epilogue ----------
    const int grp = lane >> 2, tig = lane & 3;
    #pragma unroll
    for (int nt = 0; nt < 8; ++nt) {
        const int cg = col0 + n0 + nt * 8 + 2 * tig;
        const float2 bs = *(const float2*)&bias[cg];
        #pragma unroll
        for (int mt = 0; mt < 2; ++mt) {
            const int rg = row0 + m0 + mt * 16 + grp;
            float2 v0 = make_float2(acc[mt][nt][0] + bs.x, acc[mt][nt][1] + bs.y);
            float2 v1 = make_float2(acc[mt][nt][2] + bs.x, acc[mt][nt][3] + bs.y);
            *(float2*)&out[(size_t)rg * OUTDIM + cg]       = v0;
            *(float2*)&out[(size_t)(rg + 8) * OUTDIM + cg] = v1;
        }
    }
    #undef GEN_A
    #undef KICK_W
}

extern "C" void kernel_launch(void* const* d_in, const int* in_sizes, int n_in,
                              void* d_out, int out_size) {
    const float* x    = (const float*)d_in[0];   // [32768][64]
    const float* w    = (const float*)d_in[1];   // [2][256][64][32]
    const float* bias = (const float*)d_in[2];   // [1][256]
    float* out        = (float*)d_out;           // [32768][256]

    cudaFuncSetAttribute(kan_mma, cudaFuncAttributeMaxDynamicSharedMemorySize, SMEM_SZ);

    kan_wprep<<<64, 256>>>(w);
    dim3 grid(NROWS / 128, OUTDIM / 128);        // (256, 2)
    kan_mma<<<grid, 256, SMEM_SZ>>>(x, bias, out);
}

// round 7
// speedup vs baseline: 4.3111x; 1.4517x over previous
#include <cuda_runtime.h>
#include <cstdint>
#include <math.h>

// NaiveFourierKANLayer via mma.sync fp16 split-x2:
//   y[32768,256] = A[32768,4096] @ W[4096,256] + bias
// A = Ah + Al (fp16 hi + fp16 residual, exact to ~2^-22); W = fp16 (single).
// y ~= Ah*W + Al*W  -> 2 MMAs per fragment (33% less tensor work than bf16 x3).
// A double-buffered so A-gen(i+1) overlaps compute(i) with no barrier between.

#define NROWS   32768
#define INDIM   64
#define OUTDIM  256

// ---------- helpers ----------
__device__ __forceinline__ uint32_t smem_u32(const void* p) {
    uint32_t a;
    asm("{ .reg .u64 t; cvta.to.shared.u64 t, %1; cvt.u32.u64 %0, t; }" : "=r"(a) : "l"(p));
    return a;
}
__device__ __forceinline__ uint32_t pack_f16(float e0, float e1) {   // low half = e0
    uint32_t r;
    asm("cvt.rn.f16x2.f32 %0, %1, %2;" : "=r"(r) : "f"(e1), "f"(e0));
    return r;
}
__device__ __forceinline__ float f16_low(uint32_t w) {
    float f; asm("{ .reg .b16 h; mov.b32 {h, _}, %1; cvt.f32.f16 %0, h; }" : "=f"(f) : "r"(w));
    return f;
}
__device__ __forceinline__ float f16_high(uint32_t w) {
    float f; asm("{ .reg .b16 h; mov.b32 {_, h}, %1; cvt.f32.f16 %0, h; }" : "=f"(f) : "r"(w));
    return f;
}
__device__ __forceinline__ uint32_t swz(uint32_t off) { return off ^ ((off >> 3) & 0x70); }

__device__ __forceinline__ void cpa16(uint32_t dst, const void* src) {
    asm volatile("cp.async.cg.shared.global [%0], [%1], 16;" :: "r"(dst), "l"(src) : "memory");
}
#define CP_COMMIT() asm volatile("cp.async.commit_group;" ::: "memory")
#define CP_WAIT(n)  asm volatile("cp.async.wait_group %0;" :: "n"(n) : "memory")

__device__ __forceinline__ void ldsm4(uint32_t* r, uint32_t addr) {
    asm volatile("ldmatrix.sync.aligned.m8n8.x4.shared.b16 {%0,%1,%2,%3}, [%4];"
                 : "=r"(r[0]), "=r"(r[1]), "=r"(r[2]), "=r"(r[3]) : "r"(addr));
}
__device__ __forceinline__ void mma_f16(float* d, const uint32_t* a, uint32_t b0, uint32_t b1) {
    asm volatile("mma.sync.aligned.m16n8k16.row.col.f32.f16.f16.f32 "
                 "{%0,%1,%2,%3},{%4,%5,%6,%7},{%8,%9},{%0,%1,%2,%3};"
                 : "+f"(d[0]), "+f"(d[1]), "+f"(d[2]), "+f"(d[3])
                 : "r"(a[0]), "r"(a[1]), "r"(a[2]), "r"(a[3]), "r"(b0), "r"(b1));
}

// ---------- pre-swizzled fp16 W tiles ----------
// g_wt[i][slab(o>>7)][ swz((o&127)*128 + f*2) ] : 32KB per i (2 slabs x 16KB)
__device__ __align__(1024) unsigned char g_wt[64 * 32768];

__global__ void kan_wprep(const float* __restrict__ w) {
    const int i = blockIdx.x;          // input dim
    const int o = threadIdx.x;         // output (256 threads)
    const float* pc = w + ((size_t)(0 * 256 + o) * 64 + i) * 32;   // cos weights
    const float* ps = w + ((size_t)(1 * 256 + o) * 64 + i) * 32;   // sin weights
    unsigned char* dst = g_wt + (size_t)i * 32768 + (o >> 7) * 16384;
    const uint32_t rowb = (uint32_t)(o & 127) * 128;

    #pragma unroll
    for (int half = 0; half < 2; ++half) {           // 0: cos (f 0..31), 1: sin
        const float* src = half ? ps : pc;
        #pragma unroll
        for (int g = 0; g < 4; ++g) {
            float4 v0 = *(const float4*)(src + g * 8);
            float4 v1 = *(const float4*)(src + g * 8 + 4);
            uint32_t h[4];
            h[0] = pack_f16(v0.x, v0.y); h[1] = pack_f16(v0.z, v0.w);
            h[2] = pack_f16(v1.x, v1.y); h[3] = pack_f16(v1.z, v1.w);
            uint32_t off = swz(rowb + half * 64 + g * 16);
            *(uint4*)(dst + off) = make_uint4(h[0], h[1], h[2], h[3]);
        }
    }
}

// ---------- main kernel ----------
// SMEM (96KB):
//   A buf b: hi @ b*32768 (16KB), lo @ +16384       (0 .. 64KB)
//   W buf b: 65536 + b*16384                        (64 .. 96KB)
#define SA_HI(b) ((uint32_t)(b) * 32768u)
#define SA_LO(b) (SA_HI(b) + 16384u)
#define SW(b)    (65536u + (uint32_t)(b) * 16384u)
#define SMEM_SZ  98304

__global__ __launch_bounds__(256, 2)
void kan_mma(const float* __restrict__ x, const float* __restrict__ bias,
             float* __restrict__ out) {
    extern __shared__ __align__(1024) unsigned char sm[];
    const uint32_t sb = smem_u32(sm);
    const int t = threadIdx.x, lane = t & 31, wid = t >> 5;
    const int row0 = blockIdx.x * 128, col0 = blockIdx.y * 128;

    // ---- A-gen identity: 2 threads per row, each 16 k-values ----
    const int ar_gen = t & 127;
    const int ah_gen = t >> 7;         // 0 -> k=1..16, 1 -> k=17..32
    const uint32_t genrow = (uint32_t)ar_gen * 128;
    const uint32_t genxm  = ((uint32_t)ar_gen & 7) << 4;

    const unsigned char* wslab = g_wt + (size_t)(col0 >> 7) * 16384;

    // ---- MMA identity ----
    const int wm = wid & 3, wn = wid >> 2;         // 4 x 2 warp grid
    const int m0 = wm * 32, n0 = wn * 64;
    const int a_r   = m0 + (lane & 15);
    const uint32_t a_kadd = (lane & 16) ? 16u : 0u;
    const uint32_t a_xm   = ((uint32_t)a_r & 7) << 4;
    const int b_r   = n0 + (lane & 7) + ((lane & 16) ? 8 : 0);
    const uint32_t b_kadd = (lane & 8) ? 16u : 0u;
    const uint32_t b_xm   = ((uint32_t)b_r & 7) << 4;

    float acc[2][8][4];
    #pragma unroll
    for (int mt = 0; mt < 2; ++mt)
        #pragma unroll
        for (int nt = 0; nt < 8; ++nt)
            #pragma unroll
            for (int e = 0; e < 4; ++e) acc[mt][nt][e] = 0.0f;

    // generate A(ii) (fp16 hi + fp16 residual) into buffer ii&1
    #define GEN_A(ii) do {                                                       \
        const int bb_ = (ii) & 1;                                                \
        float xv = __ldg(&x[(size_t)(row0 + ar_gen) * INDIM + (ii)]);            \
        float s1, c1; sincosf(xv, &s1, &c1);                                     \
        float ck, sk;                                                            \
        if (ah_gen == 0) { ck = c1; sk = s1; }                                   \
        else {                                                                   \
            float c2 = fmaf(c1, c1, -(s1 * s1)), s2 = 2.0f * s1 * c1;            \
            float c4 = fmaf(c2, c2, -(s2 * s2)), s4 = 2.0f * s2 * c2;            \
            float c8 = fmaf(c4, c4, -(s4 * s4)), s8 = 2.0f * s4 * c4;            \
            float c16 = fmaf(c8, c8, -(s8 * s8)), s16 = 2.0f * s8 * c8;          \
            ck = fmaf(c16, c1, -(s16 * s1)); sk = fmaf(s16, c1, c16 * s1);       \
        }                                                                        \
        uint32_t chv[8], clv[8], shv[8], slv[8];                                 \
        _Pragma("unroll")                                                        \
        for (int p = 0; p < 8; ++p) {                                            \
            float cc0 = ck, ss0 = sk;                                            \
            float cA = fmaf(ck, c1, -(sk * s1));                                 \
            float sA = fmaf(sk, c1, ck * s1);                                    \
            chv[p] = pack_f16(cc0, cA);                                          \
            clv[p] = pack_f16(cc0 - f16_low(chv[p]), cA - f16_high(chv[p]));     \
            shv[p] = pack_f16(ss0, sA);                                          \
            slv[p] = pack_f16(ss0 - f16_low(shv[p]), sA - f16_high(shv[p]));     \
            ck = fmaf(cA, c1, -(sA * s1)); sk = fmaf(sA, c1, cA * s1);           \
        }                                                                        \
        _Pragma("unroll")                                                        \
        for (int g = 0; g < 2; ++g) {                                            \
            uint32_t cb = (uint32_t)ah_gen * 32 + g * 16;                        \
            uint32_t oc = genrow + (cb ^ genxm);                                 \
            uint32_t os = genrow + ((cb + 64u) ^ genxm);                         \
            *(uint4*)(sm + SA_HI(bb_) + oc) = make_uint4(chv[4*g], chv[4*g+1], chv[4*g+2], chv[4*g+3]); \
            *(uint4*)(sm + SA_LO(bb_) + oc) = make_uint4(clv[4*g], clv[4*g+1], clv[4*g+2], clv[4*g+3]); \
            *(uint4*)(sm + SA_HI(bb_) + os) = make_uint4(shv[4*g], shv[4*g+1], shv[4*g+2], shv[4*g+3]); \
            *(uint4*)(sm + SA_LO(bb_) + os) = make_uint4(slv[4*g], slv[4*g+1], slv[4*g+2], slv[4*g+3]); \
        }                                                                        \
    } while (0)

    // kick cp.async of W(ii) into W buf ii&1 (16KB, 4 chunks/thread)
    #define KICK_W(ii) do {                                                      \
        const unsigned char* ws_ = wslab + (size_t)(ii) * 32768;                 \
        const uint32_t wd_ = SW((ii) & 1);                                       \
        _Pragma("unroll")                                                        \
        for (int j = 0; j < 4; ++j) {                                            \
            uint32_t off_ = ((uint32_t)t + j * 256u) * 16u;                      \
            cpa16(sb + wd_ + off_, ws_ + off_);                                  \
        }                                                                        \
        CP_COMMIT();                                                             \
    } while (0)

    // ---------- pipeline ----------
    KICK_W(0);
    GEN_A(0);

    #pragma unroll 1
    for (int i = 0; i < INDIM; ++i) {
        const int b = i & 1;
        __syncthreads();                 // compute(i-1) done: W(b^1), A(b^1) free
        if (i + 1 < INDIM) KICK_W(i + 1);
        if (i + 1 < INDIM) { CP_WAIT(1); } else { CP_WAIT(0); }
        __syncthreads();                 // W(i) + A(i) visible CTA-wide
        if (i + 1 < INDIM) GEN_A(i + 1); // overlaps compute(i) across warps

        // ---- compute(i) on A(b), W(b) ----
        const uint32_t Ah = sb + SA_HI(b), Al = sb + SA_LO(b);
        const uint32_t Wb = sb + SW(b);
        #pragma unroll
        for (int ks = 0; ks < 4; ++ks) {
            const uint32_t kb = ks * 32;
            const uint32_t acol = (kb + a_kadd) ^ a_xm;
            const uint32_t bcol = (kb + b_kadd) ^ b_xm;
            uint32_t ahr[2][4], alr[2][4];
            #pragma unroll
            for (int mt = 0; mt < 2; ++mt) {
                uint32_t ro = (uint32_t)(a_r + mt * 16) * 128 + acol;
                ldsm4(ahr[mt], Ah + ro);
                ldsm4(alr[mt], Al + ro);
            }
            #pragma unroll
            for (int pr = 0; pr < 4; ++pr) {
                uint32_t bh[4];
                uint32_t ro = (uint32_t)(b_r + pr * 16) * 128 + bcol;
                ldsm4(bh, Wb + ro);
                #pragma unroll
                for (int mt = 0; mt < 2; ++mt)
                    #pragma unroll
                    for (int h = 0; h < 2; ++h) {
                        float* d = acc[mt][pr * 2 + h];
                        mma_f16(d, ahr[mt], bh[h * 2], bh[h * 2 + 1]);
                        mma_f16(d, alr[mt], bh[h * 2], bh[h * 2 + 1]);
                    }
            }
        }
    }

    // ---------- epilogue ----------
    const int grp = lane >> 2, tig = lane & 3;
    #pragma unroll
    for (int nt = 0; nt < 8; ++nt) {
        const int cg = col0 + n0 + nt * 8 + 2 * tig;
        const float2 bs = *(const float2*)&bias[cg];
        #pragma unroll
        for (int mt = 0; mt < 2; ++mt) {
            const int rg = row0 + m0 + mt * 16 + grp;
            float2 v0 = make_float2(acc[mt][nt][0] + bs.x, acc[mt][nt][1] + bs.y);
            float2 v1 = make_float2(acc[mt][nt][2] + bs.x, acc[mt][nt][3] + bs.y);
            *(float2*)&out[(size_t)rg * OUTDIM + cg]       = v0;
            *(float2*)&out[(size_t)(rg + 8) * OUTDIM + cg] = v1;
        }
    }
    #undef GEN_A
    #undef KICK_W
}

extern "C" void kernel_launch(void* const* d_in, const int* in_sizes, int n_in,
                              void* d_out, int out_size) {
    const float* x    = (const float*)d_in[0];   // [32768][64]
    const float* w    = (const float*)d_in[1];   // [2][256][64][32]
    const float* bias = (const float*)d_in[2];   // [1][256]
    float* out        = (float*)d_out;           // [32768][256]

    cudaFuncSetAttribute(kan_mma, cudaFuncAttributeMaxDynamicSharedMemorySize, SMEM_SZ);

    kan_wprep<<<64, 256>>>(w);
    dim3 grid(NROWS / 128, OUTDIM / 128);        // (256, 2)
    kan_mma<<<grid, 256, SMEM_SZ>>>(x, bias, out);
}

// round 8
// speedup vs baseline: 4.4618x; 1.0349x over previous
#include <cuda_runtime.h>
#include <cstdint>
#include <math.h>

// NaiveFourierKANLayer, single fp16 MMA:
//   y[32768,256] = A[32768,4096] @ W[4096,256] + bias
// A = fp16(cos/sin features), W = fp16. One m16n8k16 MMA per fragment.
// Error model: fp16 rounding of A and W, independent -> rel_err ~3e-4 (<1e-3).
// Pipeline: double-buffered A (gen overlaps compute) + double-buffered W
// (cp.async), ONE __syncthreads per k-iteration.

#define NROWS   32768
#define INDIM   64
#define OUTDIM  256

// ---------- helpers ----------
__device__ __forceinline__ uint32_t smem_u32(const void* p) {
    uint32_t a;
    asm("{ .reg .u64 t; cvta.to.shared.u64 t, %1; cvt.u32.u64 %0, t; }" : "=r"(a) : "l"(p));
    return a;
}
__device__ __forceinline__ uint32_t pack_f16(float e0, float e1) {   // low half = e0
    uint32_t r;
    asm("cvt.rn.f16x2.f32 %0, %1, %2;" : "=r"(r) : "f"(e1), "f"(e0));
    return r;
}
__device__ __forceinline__ uint32_t swz(uint32_t off) { return off ^ ((off >> 3) & 0x70); }

__device__ __forceinline__ void cpa16(uint32_t dst, const void* src) {
    asm volatile("cp.async.cg.shared.global [%0], [%1], 16;" :: "r"(dst), "l"(src) : "memory");
}
#define CP_COMMIT() asm volatile("cp.async.commit_group;" ::: "memory")
#define CP_WAIT(n)  asm volatile("cp.async.wait_group %0;" :: "n"(n) : "memory")

__device__ __forceinline__ void ldsm4(uint32_t* r, uint32_t addr) {
    asm volatile("ldmatrix.sync.aligned.m8n8.x4.shared.b16 {%0,%1,%2,%3}, [%4];"
                 : "=r"(r[0]), "=r"(r[1]), "=r"(r[2]), "=r"(r[3]) : "r"(addr));
}
__device__ __forceinline__ void mma_f16(float* d, const uint32_t* a, uint32_t b0, uint32_t b1) {
    asm volatile("mma.sync.aligned.m16n8k16.row.col.f32.f16.f16.f32 "
                 "{%0,%1,%2,%3},{%4,%5,%6,%7},{%8,%9},{%0,%1,%2,%3};"
                 : "+f"(d[0]), "+f"(d[1]), "+f"(d[2]), "+f"(d[3])
                 : "r"(a[0]), "r"(a[1]), "r"(a[2]), "r"(a[3]), "r"(b0), "r"(b1));
}

// ---------- pre-swizzled fp16 W tiles ----------
// g_wt[i][slab(o>>7)][ swz((o&127)*128 + f*2) ] : 32KB per i (2 slabs x 16KB)
__device__ __align__(1024) unsigned char g_wt[64 * 32768];

__global__ void kan_wprep(const float* __restrict__ w) {
    const int i = blockIdx.x;          // input dim
    const int o = threadIdx.x;         // output (256 threads)
    const float* pc = w + ((size_t)(0 * 256 + o) * 64 + i) * 32;   // cos weights
    const float* ps = w + ((size_t)(1 * 256 + o) * 64 + i) * 32;   // sin weights
    unsigned char* dst = g_wt + (size_t)i * 32768 + (o >> 7) * 16384;
    const uint32_t rowb = (uint32_t)(o & 127) * 128;

    #pragma unroll
    for (int half = 0; half < 2; ++half) {           // 0: cos (f 0..31), 1: sin
        const float* src = half ? ps : pc;
        #pragma unroll
        for (int g = 0; g < 4; ++g) {
            float4 v0 = *(const float4*)(src + g * 8);
            float4 v1 = *(const float4*)(src + g * 8 + 4);
            uint32_t h[4];
            h[0] = pack_f16(v0.x, v0.y); h[1] = pack_f16(v0.z, v0.w);
            h[2] = pack_f16(v1.x, v1.y); h[3] = pack_f16(v1.z, v1.w);
            uint32_t off = swz(rowb + half * 64 + g * 16);
            *(uint4*)(dst + off) = make_uint4(h[0], h[1], h[2], h[3]);
        }
    }
}

// ---------- main kernel ----------
// SMEM (64KB):
//   A buf b: b*16384            (0 .. 32KB)
//   W buf b: 32768 + b*16384    (32 .. 64KB)
#define SA(b)    ((uint32_t)(b) * 16384u)
#define SW(b)    (32768u + (uint32_t)(b) * 16384u)
#define SMEM_SZ  65536

__global__ __launch_bounds__(256, 2)
void kan_mma(const float* __restrict__ x, const float* __restrict__ bias,
             float* __restrict__ out) {
    extern __shared__ __align__(1024) unsigned char sm[];
    const uint32_t sb = smem_u32(sm);
    const int t = threadIdx.x, lane = t & 31, wid = t >> 5;
    const int row0 = blockIdx.x * 128, col0 = blockIdx.y * 128;

    // ---- A-gen identity: 2 threads per row, each 16 k-values ----
    const int ar_gen = t & 127;
    const int ah_gen = t >> 7;         // 0 -> k=1..16, 1 -> k=17..32
    const uint32_t genrow = (uint32_t)ar_gen * 128;
    const uint32_t genxm  = ((uint32_t)ar_gen & 7) << 4;

    const unsigned char* wslab = g_wt + (size_t)(col0 >> 7) * 16384;

    // ---- MMA identity ----
    const int wm = wid & 3, wn = wid >> 2;         // 4 x 2 warp grid
    const int m0 = wm * 32, n0 = wn * 64;
    const int a_r   = m0 + (lane & 15);
    const uint32_t a_kadd = (lane & 16) ? 16u : 0u;
    const uint32_t a_xm   = ((uint32_t)a_r & 7) << 4;
    const int b_r   = n0 + (lane & 7) + ((lane & 16) ? 8 : 0);
    const uint32_t b_kadd = (lane & 8) ? 16u : 0u;
    const uint32_t b_xm   = ((uint32_t)b_r & 7) << 4;

    float acc[2][8][4];
    #pragma unroll
    for (int mt = 0; mt < 2; ++mt)
        #pragma unroll
        for (int nt = 0; nt < 8; ++nt)
            #pragma unroll
            for (int e = 0; e < 4; ++e) acc[mt][nt][e] = 0.0f;

    // generate fp16 A(ii) into buffer ii&1
    #define GEN_A(ii) do {                                                       \
        const int bb_ = (ii) & 1;                                                \
        float xv = __ldg(&x[(size_t)(row0 + ar_gen) * INDIM + (ii)]);            \
        float s1, c1; sincosf(xv, &s1, &c1);                                     \
        float ck, sk;                                                            \
        if (ah_gen == 0) { ck = c1; sk = s1; }                                   \
        else {                                                                   \
            float c2 = fmaf(c1, c1, -(s1 * s1)), s2 = 2.0f * s1 * c1;            \
            float c4 = fmaf(c2, c2, -(s2 * s2)), s4 = 2.0f * s2 * c2;            \
            float c8 = fmaf(c4, c4, -(s4 * s4)), s8 = 2.0f * s4 * c4;            \
            float c16 = fmaf(c8, c8, -(s8 * s8)), s16 = 2.0f * s8 * c8;          \
            ck = fmaf(c16, c1, -(s16 * s1)); sk = fmaf(s16, c1, c16 * s1);       \
        }                                                                        \
        uint32_t chv[8], shv[8];                                                 \
        _Pragma("unroll")                                                        \
        for (int p = 0; p < 8; ++p) {                                            \
            float cc0 = ck, ss0 = sk;                                            \
            float cA = fmaf(ck, c1, -(sk * s1));                                 \
            float sA = fmaf(sk, c1, ck * s1);                                    \
            chv[p] = pack_f16(cc0, cA);                                          \
            shv[p] = pack_f16(ss0, sA);                                          \
            ck = fmaf(cA, c1, -(sA * s1)); sk = fmaf(sA, c1, cA * s1);           \
        }                                                                        \
        _Pragma("unroll")                                                        \
        for (int g = 0; g < 2; ++g) {                                            \
            uint32_t cb = (uint32_t)ah_gen * 32 + g * 16;                        \
            uint32_t oc = genrow + (cb ^ genxm);                                 \
            uint32_t os = genrow + ((cb + 64u) ^ genxm);                         \
            *(uint4*)(sm + SA(bb_) + oc) = make_uint4(chv[4*g], chv[4*g+1], chv[4*g+2], chv[4*g+3]); \
            *(uint4*)(sm + SA(bb_) + os) = make_uint4(shv[4*g], shv[4*g+1], shv[4*g+2], shv[4*g+3]); \
        }                                                                        \
    } while (0)

    // kick cp.async of W(ii) into W buf ii&1 (16KB, 4 chunks/thread)
    #define KICK_W(ii) do {                                                      \
        const unsigned char* ws_ = wslab + (size_t)(ii) * 32768;                 \
        const uint32_t wd_ = SW((ii) & 1);                                       \
        _Pragma("unroll")                                                        \
        for (int j = 0; j < 4; ++j) {                                            \
            uint32_t off_ = ((uint32_t)t + j * 256u) * 16u;                      \
            cpa16(sb + wd_ + off_, ws_ + off_);                                  \
        }                                                                        \
        CP_COMMIT();                                                             \
    } while (0)

    // ---------- pipeline (one barrier per iteration) ----------
    KICK_W(0);
    GEN_A(0);

    #pragma unroll 1
    for (int i = 0; i < INDIM; ++i) {
        const int b = i & 1;
        CP_WAIT(0);                  // W(i) landed (this thread's chunks)
        __syncthreads();             // W(i)+A(i) visible; compute(i-1) done
        if (i + 1 < INDIM) {
            KICK_W(i + 1);           // targets buf b^1 (freed by the barrier)
            GEN_A(i + 1);            // overlaps compute(i) across warps
        }

        // ---- compute(i) on A(b), W(b) ----
        const uint32_t Ab = sb + SA(b);
        const uint32_t Wb = sb + SW(b);
        #pragma unroll
        for (int ks = 0; ks < 4; ++ks) {
            const uint32_t kb = ks * 32;
            const uint32_t acol = (kb + a_kadd) ^ a_xm;
            const uint32_t bcol = (kb + b_kadd) ^ b_xm;
            uint32_t ahr[2][4];
            #pragma unroll
            for (int mt = 0; mt < 2; ++mt)
                ldsm4(ahr[mt], Ab + (uint32_t)(a_r + mt * 16) * 128 + acol);
            #pragma unroll
            for (int pr = 0; pr < 4; ++pr) {
                uint32_t bh[4];
                ldsm4(bh, Wb + (uint32_t)(b_r + pr * 16) * 128 + bcol);
                #pragma unroll
                for (int mt = 0; mt < 2; ++mt)
                    #pragma unroll
                    for (int h = 0; h < 2; ++h)
                        mma_f16(acc[mt][pr * 2 + h], ahr[mt], bh[h * 2], bh[h * 2 + 1]);
            }
        }
    }

    // ---------- epilogue ----------
    const int grp = lane >> 2, tig = lane & 3;
    #pragma unroll
    for (int nt = 0; nt < 8; ++nt) {
        const int cg = col0 + n0 + nt * 8 + 2 * tig;
        const float2 bs = *(const float2*)&bias[cg];
        #pragma unroll
        for (int mt = 0; mt < 2; ++mt) {
            const int rg = row0 + m0 + mt * 16 + grp;
            float2 v0 = make_float2(acc[mt][nt][0] + bs.x, acc[mt][nt][1] + bs.y);
            float2 v1 = make_float2(acc[mt][nt][2] + bs.x, acc[mt][nt][3] + bs.y);
            *(float2*)&out[(size_t)rg * OUTDIM + cg]       = v0;
            *(float2*)&out[(size_t)(rg + 8) * OUTDIM + cg] = v1;
        }
    }
    #undef GEN_A
    #undef KICK_W
}

extern "C" void kernel_launch(void* const* d_in, const int* in_sizes, int n_in,
                              void* d_out, int out_size) {
    const float* x    = (const float*)d_in[0];   // [32768][64]
    const float* w    = (const float*)d_in[1];   // [2][256][64][32]
    const float* bias = (const float*)d_in[2];   // [1][256]
    float* out        = (float*)d_out;           // [32768][256]

    cudaFuncSetAttribute(kan_mma, cudaFuncAttributeMaxDynamicSharedMemorySize, SMEM_SZ);

    kan_wprep<<<64, 256>>>(w);
    dim3 grid(NROWS / 128, OUTDIM / 128);        // (256, 2)
    kan_mma<<<grid, 256, SMEM_SZ>>>(x, bias, out);
}

// round 9
// speedup vs baseline: 6.7967x; 1.5233x over previous
#include <cuda_runtime.h>
#include <cstdint>
#include <math.h>

// NaiveFourierKANLayer, warp-specialized fp16 MMA:
//   y[32768,256] = A[32768,4096] @ W[4096,256] + bias
// 512 threads/CTA: warps 0-7 = MMA consumers (pure LDSM+HMMA stream),
// warps 8-15 = producers (A-gen via MUFU-seeded rotation recurrence + W cp.async).
// Handshake: named barriers (FULL/EMPTY per buffer), producers run 1 iter ahead.

#define NROWS   32768
#define INDIM   64
#define OUTDIM  256

// ---------- helpers ----------
__device__ __forceinline__ uint32_t smem_u32(const void* p) {
    uint32_t a;
    asm("{ .reg .u64 t; cvta.to.shared.u64 t, %1; cvt.u32.u64 %0, t; }" : "=r"(a) : "l"(p));
    return a;
}
__device__ __forceinline__ uint32_t pack_f16(float e0, float e1) {   // low half = e0
    uint32_t r;
    asm("cvt.rn.f16x2.f32 %0, %1, %2;" : "=r"(r) : "f"(e1), "f"(e0));
    return r;
}
__device__ __forceinline__ uint32_t swz(uint32_t off) { return off ^ ((off >> 3) & 0x70); }

__device__ __forceinline__ void cpa16(uint32_t dst, const void* src) {
    asm volatile("cp.async.cg.shared.global [%0], [%1], 16;" :: "r"(dst), "l"(src) : "memory");
}
#define CP_COMMIT() asm volatile("cp.async.commit_group;" ::: "memory")
#define CP_WAIT0()  asm volatile("cp.async.wait_group 0;" ::: "memory")

// named split barriers, whole-CTA count (512)
#define BAR_SYNC(id)   asm volatile("bar.sync %0, 512;"   :: "r"(id) : "memory")
#define BAR_ARRIVE(id) asm volatile("bar.arrive %0, 512;" :: "r"(id) : "memory")
// FULL[b] = 1+b (producer arrives, consumer syncs)
// EMPTY[b] = 3+b (consumer arrives, producer syncs)

__device__ __forceinline__ void ldsm4(uint32_t* r, uint32_t addr) {
    asm volatile("ldmatrix.sync.aligned.m8n8.x4.shared.b16 {%0,%1,%2,%3}, [%4];"
                 : "=r"(r[0]), "=r"(r[1]), "=r"(r[2]), "=r"(r[3]) : "r"(addr));
}
__device__ __forceinline__ void mma_f16(float* d, const uint32_t* a, uint32_t b0, uint32_t b1) {
    asm volatile("mma.sync.aligned.m16n8k16.row.col.f32.f16.f16.f32 "
                 "{%0,%1,%2,%3},{%4,%5,%6,%7},{%8,%9},{%0,%1,%2,%3};"
                 : "+f"(d[0]), "+f"(d[1]), "+f"(d[2]), "+f"(d[3])
                 : "r"(a[0]), "r"(a[1]), "r"(a[2]), "r"(a[3]), "r"(b0), "r"(b1));
}

// ---------- pre-swizzled fp16 W tiles ----------
// g_wt[i][slab(o>>7)][ swz((o&127)*128 + f*2) ] : 32KB per i (2 slabs x 16KB)
__device__ __align__(1024) unsigned char g_wt[64 * 32768];

__global__ void kan_wprep(const float* __restrict__ w) {
    const int i = blockIdx.x;
    const int o = threadIdx.x;
    const float* pc = w + ((size_t)(0 * 256 + o) * 64 + i) * 32;
    const float* ps = w + ((size_t)(1 * 256 + o) * 64 + i) * 32;
    unsigned char* dst = g_wt + (size_t)i * 32768 + (o >> 7) * 16384;
    const uint32_t rowb = (uint32_t)(o & 127) * 128;

    #pragma unroll
    for (int half = 0; half < 2; ++half) {
        const float* src = half ? ps : pc;
        #pragma unroll
        for (int g = 0; g < 4; ++g) {
            float4 v0 = *(const float4*)(src + g * 8);
            float4 v1 = *(const float4*)(src + g * 8 + 4);
            uint32_t h[4];
            h[0] = pack_f16(v0.x, v0.y); h[1] = pack_f16(v0.z, v0.w);
            h[2] = pack_f16(v1.x, v1.y); h[3] = pack_f16(v1.z, v1.w);
            uint32_t off = swz(rowb + half * 64 + g * 16);
            *(uint4*)(dst + off) = make_uint4(h[0], h[1], h[2], h[3]);
        }
    }
}

// ---------- main kernel ----------
// SMEM (64KB): A buf b @ b*16384; W buf b @ 32768 + b*16384
#define SA(b)    ((uint32_t)(b) * 16384u)
#define SW(b)    (32768u + (uint32_t)(b) * 16384u)
#define SMEM_SZ  65536

__global__ __launch_bounds__(512, 1)
void kan_mma(const float* __restrict__ x, const float* __restrict__ bias,
             float* __restrict__ out) {
    extern __shared__ __align__(1024) unsigned char sm[];
    const uint32_t sb = smem_u32(sm);
    const int t = threadIdx.x, lane = t & 31, wid = t >> 5;
    const int row0 = blockIdx.x * 128, col0 = blockIdx.y * 128;

    if (wid >= 8) {
        // ================= PRODUCERS (warps 8-15, 256 threads) =================
        const int pt = t - 256;
        const int ar = pt & 127;           // row
        const int ah = pt >> 7;            // 0 -> k=1..16, 1 -> k=17..32
        const uint32_t genrow = (uint32_t)ar * 128;
        const uint32_t genxm  = ((uint32_t)ar & 7) << 4;
        const unsigned char* wslab = g_wt + (size_t)(col0 >> 7) * 16384;
        const float* xrow = x + (size_t)(row0 + ar) * INDIM;

        float xnext = __ldg(xrow);
        #pragma unroll 1
        for (int i = 0; i < INDIM; ++i) {
            const int b = i & 1;
            if (i >= 2) BAR_SYNC(3 + b);              // consumers freed bufs b

            // W(i) -> SW(b): 16KB, 4x16B per producer thread
            {
                const unsigned char* ws = wslab + (size_t)i * 32768;
                const uint32_t wd = sb + SW(b);
                #pragma unroll
                for (int j = 0; j < 4; ++j) {
                    uint32_t off = ((uint32_t)pt + j * 256u) * 16u;
                    cpa16(wd + off, ws + off);
                }
                CP_COMMIT();
            }

            // A(i) -> SA(b)
            float xv = xnext;
            if (i + 1 < INDIM) xnext = __ldg(xrow + i + 1);
            float c1, s1, ck, sk;
            __sincosf(xv, &s1, &c1);
            if (ah) { float a17 = 17.0f * xv; sk = __sinf(a17); ck = __cosf(a17); }
            else    { ck = c1; sk = s1; }
            uint32_t chv[8], shv[8];
            #pragma unroll
            for (int p = 0; p < 8; ++p) {
                float cc0 = ck, ss0 = sk;
                float cA = fmaf(ck, c1, -(sk * s1));
                float sA = fmaf(sk, c1, ck * s1);
                chv[p] = pack_f16(cc0, cA);
                shv[p] = pack_f16(ss0, sA);
                ck = fmaf(cA, c1, -(sA * s1)); sk = fmaf(sA, c1, cA * s1);
            }
            const uint32_t ab = SA(b);
            #pragma unroll
            for (int g = 0; g < 2; ++g) {
                uint32_t cb = (uint32_t)ah * 32 + g * 16;
                uint32_t oc = genrow + (cb ^ genxm);
                uint32_t os = genrow + ((cb + 64u) ^ genxm);
                *(uint4*)(sm + ab + oc) = make_uint4(chv[4*g], chv[4*g+1], chv[4*g+2], chv[4*g+3]);
                *(uint4*)(sm + ab + os) = make_uint4(shv[4*g], shv[4*g+1], shv[4*g+2], shv[4*g+3]);
            }

            CP_WAIT0();                                // W(i) landed (this thread)
            BAR_ARRIVE(1 + b);                         // publish FULL(b)
        }
        return;
    }

    // ================= CONSUMERS (warps 0-7) =================
    const int wm = wid & 3, wn = wid >> 2;             // 4 x 2 warp grid
    const int m0 = wm * 32, n0 = wn * 64;
    const int a_r   = m0 + (lane & 15);
    const uint32_t a_kadd = (lane & 16) ? 16u : 0u;
    const uint32_t a_xm   = ((uint32_t)a_r & 7) << 4;
    const int b_r   = n0 + (lane & 7) + ((lane & 16) ? 8 : 0);
    const uint32_t b_kadd = (lane & 8) ? 16u : 0u;
    const uint32_t b_xm   = ((uint32_t)b_r & 7) << 4;

    float acc[2][8][4];
    #pragma unroll
    for (int mt = 0; mt < 2; ++mt)
        #pragma unroll
        for (int nt = 0; nt < 8; ++nt)
            #pragma unroll
            for (int e = 0; e < 4; ++e) acc[mt][nt][e] = 0.0f;

    #pragma unroll 1
    for (int i = 0; i < INDIM; ++i) {
        const int b = i & 1;
        BAR_SYNC(1 + b);                               // wait FULL(b)
        const uint32_t Ab = sb + SA(b);
        const uint32_t Wb = sb + SW(b);
        #pragma unroll
        for (int ks = 0; ks < 4; ++ks) {
            const uint32_t kb = ks * 32;
            const uint32_t acol = (kb + a_kadd) ^ a_xm;
            const uint32_t bcol = (kb + b_kadd) ^ b_xm;
            uint32_t ahr[2][4];
            #pragma unroll
            for (int mt = 0; mt < 2; ++mt)
                ldsm4(ahr[mt], Ab + (uint32_t)(a_r + mt * 16) * 128 + acol);
            #pragma unroll
            for (int pr = 0; pr < 4; ++pr) {
                uint32_t bh[4];
                ldsm4(bh, Wb + (uint32_t)(b_r + pr * 16) * 128 + bcol);
                #pragma unroll
                for (int mt = 0; mt < 2; ++mt)
                    #pragma unroll
                    for (int h = 0; h < 2; ++h)
                        mma_f16(acc[mt][pr * 2 + h], ahr[mt], bh[h * 2], bh[h * 2 + 1]);
            }
        }
        BAR_ARRIVE(3 + b);                             // release EMPTY(b)
    }

    // ---------- epilogue ----------
    const int grp = lane >> 2, tig = lane & 3;
    #pragma unroll
    for (int nt = 0; nt < 8; ++nt) {
        const int cg = col0 + n0 + nt * 8 + 2 * tig;
        const float2 bs = *(const float2*)&bias[cg];
        #pragma unroll
        for (int mt = 0; mt < 2; ++mt) {
            const int rg = row0 + m0 + mt * 16 + grp;
            float2 v0 = make_float2(acc[mt][nt][0] + bs.x, acc[mt][nt][1] + bs.y);
            float2 v1 = make_float2(acc[mt][nt][2] + bs.x, acc[mt][nt][3] + bs.y);
            *(float2*)&out[(size_t)rg * OUTDIM + cg]       = v0;
            *(float2*)&out[(size_t)(rg + 8) * OUTDIM + cg] = v1;
        }
    }
}

extern "C" void kernel_launch(void* const* d_in, const int* in_sizes, int n_in,
                              void* d_out, int out_size) {
    const float* x    = (const float*)d_in[0];   // [32768][64]
    const float* w    = (const float*)d_in[1];   // [2][256][64][32]
    const float* bias = (const float*)d_in[2];   // [1][256]
    float* out        = (float*)d_out;           // [32768][256]

    cudaFuncSetAttribute(kan_mma, cudaFuncAttributeMaxDynamicSharedMemorySize, SMEM_SZ);

    kan_wprep<<<64, 256>>>(w);
    dim3 grid(NROWS / 128, OUTDIM / 128);        // (256, 2)
    kan_mma<<<grid, 512, SMEM_SZ>>>(x, bias, out);
}